// round 3
// baseline (speedup 1.0000x reference)
#include <cuda_runtime.h>
#include <math.h>

#define T    2048
#define D    1024
#define E    16
#define F    1024
#define KSEL 4
#define NG   4
#define EPG  4
#define SHF  2048
#define SCALEF 2.5f

// ---------------- scratch (static device globals; no allocs allowed) ----------
__device__ int   g_cnt[E];
__device__ int   g_tok[E * T];
__device__ float g_wt [E * T];
__device__ float g_act[(size_t)E * T * F];      // 128 MB routed activations
__device__ float g_shact[(size_t)T * SHF];      // 16 MB shared-expert activations

// ---------------- reset counters ---------------------------------------------
__global__ void zero_cnt_kernel() {
    if (threadIdx.x < E) g_cnt[threadIdx.x] = 0;
}

// ---------------- router: warp per token -------------------------------------
__global__ void router_kernel(const float* __restrict__ x,
                              const float* __restrict__ rw,
                              const float* __restrict__ bias) {
    int t    = blockIdx.x * (blockDim.x >> 5) + (threadIdx.x >> 5);
    int lane = threadIdx.x & 31;
    if (t >= T) return;
    const float4* xr = (const float4*)(x + (size_t)t * D);

    float logit[E];
#pragma unroll
    for (int e = 0; e < E; e++) {
        const float4* w = (const float4*)(rw + (size_t)e * D);
        float p = 0.f;
#pragma unroll
        for (int k = lane; k < D / 4; k += 32) {
            float4 a = xr[k], b = w[k];
            p += a.x * b.x + a.y * b.y + a.z * b.z + a.w * b.w;
        }
#pragma unroll
        for (int o = 16; o > 0; o >>= 1) p += __shfl_xor_sync(0xffffffffu, p, o);
        logit[e] = p;
    }

    if (lane == 0) {
        float scores[E], s[E];
#pragma unroll
        for (int e = 0; e < E; e++) {
            scores[e] = 1.f / (1.f + expf(-logit[e]));
            s[e]      = scores[e] + bias[e];
        }
        // group score = sum of top-2 within each group of EPG=4
        float gs[NG];
#pragma unroll
        for (int g = 0; g < NG; g++) {
            float m1 = -1e30f, m2 = -1e30f;
#pragma unroll
            for (int j = 0; j < EPG; j++) {
                float v = s[g * EPG + j];
                if (v > m1) { m2 = m1; m1 = v; }
                else if (v > m2) { m2 = v; }
            }
            gs[g] = m1 + m2;
        }
        // top-2 groups (strict >, lowest index on tie — matches jax top_k)
        int g1 = 0; float b1 = -1e30f;
#pragma unroll
        for (int g = 0; g < NG; g++) if (gs[g] > b1) { b1 = gs[g]; g1 = g; }
        int g2 = -1; float b2 = -1e30f;
#pragma unroll
        for (int g = 0; g < NG; g++) if (g != g1 && gs[g] > b2) { b2 = gs[g]; g2 = g; }

        float masked[E];
#pragma unroll
        for (int e = 0; e < E; e++) {
            int g = e / EPG;
            masked[e] = (g == g1 || g == g2) ? s[e] : -1.0f;
        }
        // top-4 experts of masked
        int idx[KSEL];
        bool taken[E];
#pragma unroll
        for (int e = 0; e < E; e++) taken[e] = false;
#pragma unroll
        for (int k = 0; k < KSEL; k++) {
            float best = -1e30f; int bi = 0;
#pragma unroll
            for (int e = 0; e < E; e++)
                if (!taken[e] && masked[e] > best) { best = masked[e]; bi = e; }
            taken[bi] = true;
            idx[k] = bi;
        }
        float tw[KSEL], sum = 0.f;
#pragma unroll
        for (int k = 0; k < KSEL; k++) { tw[k] = scores[idx[k]]; sum += tw[k]; }
        float inv = SCALEF / (sum + 1e-20f);
#pragma unroll
        for (int k = 0; k < KSEL; k++) {
            int e = idx[k];
            int pos = atomicAdd(&g_cnt[e], 1);
            g_tok[e * T + pos] = t;
            g_wt [e * T + pos] = tw[k] * inv;
        }
    }
}

// ---------------- routed gate/up GEMM + SiLU*up epilogue ---------------------
// tile 64x64, BK=16, 256 threads, 4x4 micro-tile per thread for BOTH gate & up
__global__ void __launch_bounds__(256)
gateup_kernel(const float* __restrict__ x,
              const float* __restrict__ gate_w,
              const float* __restrict__ up_w) {
    const int e   = blockIdx.z;
    const int cnt = g_cnt[e];
    const int m0  = blockIdx.y * 64;
    if (m0 >= cnt) return;
    const int n0  = blockIdx.x * 64;

    __shared__ float As[16][64];
    __shared__ float Bg[16][64];
    __shared__ float Bu[16][64];
    __shared__ int   rows[64];

    const int tid = threadIdx.x;
    if (tid < 64) {
        int i = m0 + tid;
        rows[tid] = g_tok[e * T + (i < cnt ? i : cnt - 1)];
    }
    __syncthreads();

    const int tx = tid & 15, ty = tid >> 4;
    const int ar = tid >> 2, ac = (tid & 3) * 4;
    const int br = tid >> 4, bc = (tid & 15) * 4;

    const float* gw = gate_w + (size_t)e * D * F;
    const float* uw = up_w   + (size_t)e * D * F;
    const float* xA = x + (size_t)rows[ar] * D + ac;

    float ag[16], au[16];
#pragma unroll
    for (int i = 0; i < 16; i++) { ag[i] = 0.f; au[i] = 0.f; }

    for (int k0 = 0; k0 < D; k0 += 16) {
        float4 av  = *(const float4*)(xA + k0);
        float4 bgv = *(const float4*)(gw + (size_t)(k0 + br) * F + n0 + bc);
        float4 buv = *(const float4*)(uw + (size_t)(k0 + br) * F + n0 + bc);
        As[ac + 0][ar] = av.x; As[ac + 1][ar] = av.y;
        As[ac + 2][ar] = av.z; As[ac + 3][ar] = av.w;
        *(float4*)&Bg[br][bc] = bgv;
        *(float4*)&Bu[br][bc] = buv;
        __syncthreads();
#pragma unroll
        for (int k = 0; k < 16; k++) {
            float4 a = *(const float4*)&As[k][ty * 4];
            float4 b = *(const float4*)&Bg[k][tx * 4];
            float4 c = *(const float4*)&Bu[k][tx * 4];
            float aa[4] = {a.x, a.y, a.z, a.w};
            float bb[4] = {b.x, b.y, b.z, b.w};
            float cc[4] = {c.x, c.y, c.z, c.w};
#pragma unroll
            for (int i = 0; i < 4; i++)
#pragma unroll
                for (int j = 0; j < 4; j++) {
                    ag[i * 4 + j] += aa[i] * bb[j];
                    au[i * 4 + j] += aa[i] * cc[j];
                }
        }
        __syncthreads();
    }
#pragma unroll
    for (int i = 0; i < 4; i++) {
        int m = m0 + ty * 4 + i;
        if (m < cnt) {
            float* dst = g_act + ((size_t)e * T + m) * F + n0 + tx * 4;
            float4 o;
            float g, u;
            g = ag[i*4+0]; u = au[i*4+0]; o.x = g / (1.f + expf(-g)) * u;
            g = ag[i*4+1]; u = au[i*4+1]; o.y = g / (1.f + expf(-g)) * u;
            g = ag[i*4+2]; u = au[i*4+2]; o.z = g / (1.f + expf(-g)) * u;
            g = ag[i*4+3]; u = au[i*4+3]; o.w = g / (1.f + expf(-g)) * u;
            *(float4*)dst = o;
        }
    }
}

// ---------------- routed down GEMM + weighted atomic combine -----------------
__global__ void __launch_bounds__(256)
down_kernel(const float* __restrict__ down_w, float* __restrict__ out) {
    const int e   = blockIdx.z;
    const int cnt = g_cnt[e];
    const int m0  = blockIdx.y * 64;
    if (m0 >= cnt) return;
    const int n0  = blockIdx.x * 64;

    __shared__ float As[16][64];
    __shared__ float Bs[16][64];

    const int tid = threadIdx.x;
    const int tx = tid & 15, ty = tid >> 4;
    const int ar = tid >> 2, ac = (tid & 3) * 4;
    const int br = tid >> 4, bc = (tid & 15) * 4;

    const float* A  = g_act + ((size_t)e * T + m0) * F;
    const float* Bp = down_w + (size_t)e * F * D;

    float acc[16];
#pragma unroll
    for (int i = 0; i < 16; i++) acc[i] = 0.f;

    for (int k0 = 0; k0 < F; k0 += 16) {
        float4 av = *(const float4*)(A + (size_t)ar * F + k0 + ac);
        float4 bv = *(const float4*)(Bp + (size_t)(k0 + br) * D + n0 + bc);
        As[ac + 0][ar] = av.x; As[ac + 1][ar] = av.y;
        As[ac + 2][ar] = av.z; As[ac + 3][ar] = av.w;
        *(float4*)&Bs[br][bc] = bv;
        __syncthreads();
#pragma unroll
        for (int k = 0; k < 16; k++) {
            float4 a = *(const float4*)&As[k][ty * 4];
            float4 b = *(const float4*)&Bs[k][tx * 4];
            float aa[4] = {a.x, a.y, a.z, a.w};
            float bb[4] = {b.x, b.y, b.z, b.w};
#pragma unroll
            for (int i = 0; i < 4; i++)
#pragma unroll
                for (int j = 0; j < 4; j++)
                    acc[i * 4 + j] += aa[i] * bb[j];
        }
        __syncthreads();
    }
#pragma unroll
    for (int i = 0; i < 4; i++) {
        int m = m0 + ty * 4 + i;
        if (m < cnt) {
            int   t = g_tok[e * T + m];
            float w = g_wt [e * T + m];
            float* dst = out + (size_t)t * D + n0 + tx * 4;
            atomicAdd(dst + 0, w * acc[i * 4 + 0]);
            atomicAdd(dst + 1, w * acc[i * 4 + 1]);
            atomicAdd(dst + 2, w * acc[i * 4 + 2]);
            atomicAdd(dst + 3, w * acc[i * 4 + 3]);
        }
    }
}

// ---------------- shared expert gate/up --------------------------------------
__global__ void __launch_bounds__(256)
shgateup_kernel(const float* __restrict__ x,
                const float* __restrict__ gw,
                const float* __restrict__ uw) {
    const int m0 = blockIdx.y * 64;
    const int n0 = blockIdx.x * 64;

    __shared__ float As[16][64];
    __shared__ float Bg[16][64];
    __shared__ float Bu[16][64];

    const int tid = threadIdx.x;
    const int tx = tid & 15, ty = tid >> 4;
    const int ar = tid >> 2, ac = (tid & 3) * 4;
    const int br = tid >> 4, bc = (tid & 15) * 4;

    const float* xA = x + (size_t)(m0 + ar) * D + ac;

    float ag[16], au[16];
#pragma unroll
    for (int i = 0; i < 16; i++) { ag[i] = 0.f; au[i] = 0.f; }

    for (int k0 = 0; k0 < D; k0 += 16) {
        float4 av  = *(const float4*)(xA + k0);
        float4 bgv = *(const float4*)(gw + (size_t)(k0 + br) * SHF + n0 + bc);
        float4 buv = *(const float4*)(uw + (size_t)(k0 + br) * SHF + n0 + bc);
        As[ac + 0][ar] = av.x; As[ac + 1][ar] = av.y;
        As[ac + 2][ar] = av.z; As[ac + 3][ar] = av.w;
        *(float4*)&Bg[br][bc] = bgv;
        *(float4*)&Bu[br][bc] = buv;
        __syncthreads();
#pragma unroll
        for (int k = 0; k < 16; k++) {
            float4 a = *(const float4*)&As[k][ty * 4];
            float4 b = *(const float4*)&Bg[k][tx * 4];
            float4 c = *(const float4*)&Bu[k][tx * 4];
            float aa[4] = {a.x, a.y, a.z, a.w};
            float bb[4] = {b.x, b.y, b.z, b.w};
            float cc[4] = {c.x, c.y, c.z, c.w};
#pragma unroll
            for (int i = 0; i < 4; i++)
#pragma unroll
                for (int j = 0; j < 4; j++) {
                    ag[i * 4 + j] += aa[i] * bb[j];
                    au[i * 4 + j] += aa[i] * cc[j];
                }
        }
        __syncthreads();
    }
#pragma unroll
    for (int i = 0; i < 4; i++) {
        int m = m0 + ty * 4 + i;
        float* dst = g_shact + (size_t)m * SHF + n0 + tx * 4;
        float4 o;
        float g, u;
        g = ag[i*4+0]; u = au[i*4+0]; o.x = g / (1.f + expf(-g)) * u;
        g = ag[i*4+1]; u = au[i*4+1]; o.y = g / (1.f + expf(-g)) * u;
        g = ag[i*4+2]; u = au[i*4+2]; o.z = g / (1.f + expf(-g)) * u;
        g = ag[i*4+3]; u = au[i*4+3]; o.w = g / (1.f + expf(-g)) * u;
        *(float4*)dst = o;
    }
}

// ---------------- shared expert down (initializes out with plain stores) -----
__global__ void __launch_bounds__(256)
shdown_kernel(const float* __restrict__ dw, float* __restrict__ out) {
    const int m0 = blockIdx.y * 64;
    const int n0 = blockIdx.x * 64;

    __shared__ float As[16][64];
    __shared__ float Bs[16][64];

    const int tid = threadIdx.x;
    const int tx = tid & 15, ty = tid >> 4;
    const int ar = tid >> 2, ac = (tid & 3) * 4;
    const int br = tid >> 4, bc = (tid & 15) * 4;

    const float* A = g_shact + (size_t)(m0 + ar) * SHF + ac;

    float acc[16];
#pragma unroll
    for (int i = 0; i < 16; i++) acc[i] = 0.f;

    for (int k0 = 0; k0 < SHF; k0 += 16) {
        float4 av = *(const float4*)(A + k0);
        float4 bv = *(const float4*)(dw + (size_t)(k0 + br) * D + n0 + bc);
        As[ac + 0][ar] = av.x; As[ac + 1][ar] = av.y;
        As[ac + 2][ar] = av.z; As[ac + 3][ar] = av.w;
        *(float4*)&Bs[br][bc] = bv;
        __syncthreads();
#pragma unroll
        for (int k = 0; k < 16; k++) {
            float4 a = *(const float4*)&As[k][ty * 4];
            float4 b = *(const float4*)&Bs[k][tx * 4];
            float aa[4] = {a.x, a.y, a.z, a.w};
            float bb[4] = {b.x, b.y, b.z, b.w};
#pragma unroll
            for (int i = 0; i < 4; i++)
#pragma unroll
                for (int j = 0; j < 4; j++)
                    acc[i * 4 + j] += aa[i] * bb[j];
        }
        __syncthreads();
    }
#pragma unroll
    for (int i = 0; i < 4; i++) {
        int m = m0 + ty * 4 + i;
        float* dst = out + (size_t)m * D + n0 + tx * 4;
        float4 o = {acc[i*4+0], acc[i*4+1], acc[i*4+2], acc[i*4+3]};
        *(float4*)dst = o;
    }
}

// ---------------- launch ------------------------------------------------------
extern "C" void kernel_launch(void* const* d_in, const int* in_sizes, int n_in,
                              void* d_out, int out_size) {
    const float* x      = (const float*)d_in[0];
    const float* rw     = (const float*)d_in[1];
    const float* bias   = (const float*)d_in[2];
    const float* gate_w = (const float*)d_in[3];
    const float* up_w   = (const float*)d_in[4];
    const float* down_w = (const float*)d_in[5];
    const float* shg    = (const float*)d_in[6];
    const float* shu    = (const float*)d_in[7];
    const float* shd    = (const float*)d_in[8];
    float* out = (float*)d_out;

    zero_cnt_kernel<<<1, 32>>>();
    router_kernel<<<T / 8, 256>>>(x, rw, bias);
    gateup_kernel<<<dim3(F / 64, T / 64, E), 256>>>(x, gate_w, up_w);
    shgateup_kernel<<<dim3(SHF / 64, T / 64), 256>>>(x, shg, shu);
    shdown_kernel<<<dim3(D / 64, T / 64), 256>>>(shd, out);   // writes out (init)
    down_kernel<<<dim3(D / 64, T / 64, E), 256>>>(down_w, out); // atomic combine
}

// round 5
// speedup vs baseline: 1.6183x; 1.6183x over previous
#include <cuda_runtime.h>
#include <math.h>
#include <stdint.h>

#define T    2048
#define D    1024
#define E    16
#define KSEL 4
#define NG   4
#define EPG  4
#define F    1024
#define SHF  2048
#define SCALEF 2.5f

// ---------------- scratch ------------------------------------------------------
__device__ int   g_cnt[E];
__device__ int   g_tok[E * T];
__device__ float g_wt [E * T];
__device__ float g_act [(size_t)E * T * F];   // routed activations
__device__ float g_shact[(size_t)T * SHF];    // shared-expert activations

// ---------------- helpers ------------------------------------------------------
__device__ __forceinline__ uint32_t f2tf32(float x) {
    uint32_t o;
    asm("cvt.rna.tf32.f32 %0, %1;" : "=r"(o) : "f"(x));
    return o;
}
__device__ __forceinline__ float silu(float g) { return g / (1.f + expf(-g)); }

__device__ __forceinline__ void mma_tf32(float c[4], const uint32_t a[4],
                                         const uint32_t b[2]) {
    asm volatile(
        "mma.sync.aligned.m16n8k8.row.col.f32.tf32.tf32.f32 "
        "{%0,%1,%2,%3}, {%4,%5,%6,%7}, {%8,%9}, {%0,%1,%2,%3};"
        : "+f"(c[0]), "+f"(c[1]), "+f"(c[2]), "+f"(c[3])
        : "r"(a[0]), "r"(a[1]), "r"(a[2]), "r"(a[3]), "r"(b[0]), "r"(b[1]));
}

// epilogue modes
#define EPI_RAW       0   // store raw fp32 accumulators
#define EPI_SILU_MUL  1   // read u from O, store silu(acc)*u in place
#define EPI_STORE     2   // plain store (dense)
#define EPI_ATOMIC    3   // weighted atomicAdd combine (routed down)

#define ALD 36    // As leading dim (floats): banks (4*row+col)%32 all-distinct
#define BLD 136   // Bs leading dim (floats): banks (8*row+col)%32 all-distinct

// ---------------- tf32 mma.sync GEMM ------------------------------------------
// C[128,128] tile = A[128,K] * B[K,128];  B global layout [K][N] (k-major).
template <int MODE, bool GATHER>
__global__ void __launch_bounds__(256)
gemm_mma(const float* __restrict__ A, const float* __restrict__ B,
         float* __restrict__ O, int K, size_t b_exp_stride, int Bld,
         int Ostride, int use_expert) {
    const int e   = use_expert ? blockIdx.z : 0;
    const int cnt = use_expert ? g_cnt[e] : T;
    const int m0  = blockIdx.y * 128;
    if (m0 >= cnt) return;
    const int n0  = blockIdx.x * 128;

    __shared__ float As[128][ALD];
    __shared__ float Bs[32][BLD];
    __shared__ int   rows[128];

    const int tid    = threadIdx.x;
    const int lane   = tid & 31;
    const int wid    = tid >> 5;
    const int warp_m = wid & 3;          // 4 warps along M (32 rows each)
    const int warp_n = wid >> 2;         // 2 warps along N (64 cols each)

    if (tid < 128) {
        if (GATHER) {
            int i = m0 + tid;
            rows[tid] = g_tok[e * T + (i < cnt ? i : cnt - 1)];
        } else {
            rows[tid] = m0 + tid;
        }
    }
    __syncthreads();

    const float* abase = A + (use_expert && !GATHER ? (size_t)e * T * K : 0);
    const float* bbase = B + (use_expert ? (size_t)e * b_exp_stride : 0) + n0;

    // load mapping: A row = tid/2, two half-rows of 16 floats; B row = tid/8, 64B
    const int aRow = tid >> 1, aCol = (tid & 1) * 16;
    const int bRow = tid >> 3, bCol = (tid & 7) * 16;
    const float* aptr = abase + (size_t)rows[aRow] * K + aCol;

    float4 pa[4], pb[4];
#pragma unroll
    for (int i = 0; i < 4; i++) pa[i] = *(const float4*)(aptr + i * 4);
#pragma unroll
    for (int i = 0; i < 4; i++)
        pb[i] = *(const float4*)(bbase + (size_t)bRow * Bld + bCol + i * 4);

    float acc[2][8][4];
#pragma unroll
    for (int mt = 0; mt < 2; mt++)
#pragma unroll
        for (int nt = 0; nt < 8; nt++)
#pragma unroll
            for (int j = 0; j < 4; j++) acc[mt][nt][j] = 0.f;

    for (int k0 = 0; k0 < K; k0 += 32) {
        // store prefetched tile (tf32-rounded)
#pragma unroll
        for (int i = 0; i < 4; i++) {
            float4 v = pa[i];
            uint32_t* d = (uint32_t*)&As[aRow][aCol + i * 4];
            d[0] = f2tf32(v.x); d[1] = f2tf32(v.y);
            d[2] = f2tf32(v.z); d[3] = f2tf32(v.w);
        }
#pragma unroll
        for (int i = 0; i < 4; i++) {
            float4 v = pb[i];
            uint32_t* d = (uint32_t*)&Bs[bRow][bCol + i * 4];
            d[0] = f2tf32(v.x); d[1] = f2tf32(v.y);
            d[2] = f2tf32(v.z); d[3] = f2tf32(v.w);
        }
        __syncthreads();

        if (k0 + 32 < K) {
#pragma unroll
            for (int i = 0; i < 4; i++)
                pa[i] = *(const float4*)(aptr + k0 + 32 + i * 4);
#pragma unroll
            for (int i = 0; i < 4; i++)
                pb[i] = *(const float4*)(bbase + (size_t)(k0 + 32 + bRow) * Bld +
                                         bCol + i * 4);
        }

#pragma unroll
        for (int ks = 0; ks < 4; ks++) {
            const int kb = ks * 8;
            uint32_t af[2][4], bf[8][2];
#pragma unroll
            for (int mt = 0; mt < 2; mt++) {
                int r = warp_m * 32 + mt * 16 + (lane >> 2);
                int c = kb + (lane & 3);
                af[mt][0] = __float_as_uint(As[r][c]);
                af[mt][1] = __float_as_uint(As[r + 8][c]);
                af[mt][2] = __float_as_uint(As[r][c + 4]);
                af[mt][3] = __float_as_uint(As[r + 8][c + 4]);
            }
#pragma unroll
            for (int nt = 0; nt < 8; nt++) {
                int cc = warp_n * 64 + nt * 8 + (lane >> 2);
                int rr = kb + (lane & 3);
                bf[nt][0] = __float_as_uint(Bs[rr][cc]);
                bf[nt][1] = __float_as_uint(Bs[rr + 4][cc]);
            }
#pragma unroll
            for (int mt = 0; mt < 2; mt++)
#pragma unroll
                for (int nt = 0; nt < 8; nt++)
                    mma_tf32(acc[mt][nt], af[mt], bf[nt]);
        }
        __syncthreads();
    }

    // ---------------- epilogue ----------------
#pragma unroll
    for (int mt = 0; mt < 2; mt++) {
#pragma unroll
        for (int half = 0; half < 2; half++) {
            const int m = m0 + warp_m * 32 + mt * 16 + (lane >> 2) + half * 8;
            if (m >= cnt) continue;
            int   tok = m;
            float w   = 1.f;
            if (MODE == EPI_ATOMIC) { tok = g_tok[e * T + m]; w = g_wt[e * T + m]; }
            float* orow;
            if (MODE == EPI_ATOMIC || MODE == EPI_STORE)
                orow = O + (size_t)tok * Ostride + n0;
            else if (use_expert)
                orow = O + ((size_t)e * T + m) * Ostride + n0;
            else
                orow = O + (size_t)m * Ostride + n0;
#pragma unroll
            for (int nt = 0; nt < 8; nt++) {
                const int c = warp_n * 64 + nt * 8 + 2 * (lane & 3);
                float v0 = acc[mt][nt][half * 2 + 0];
                float v1 = acc[mt][nt][half * 2 + 1];
                if (MODE == EPI_RAW || MODE == EPI_STORE) {
                    float2 o = {v0, v1};
                    *(float2*)(orow + c) = o;
                } else if (MODE == EPI_SILU_MUL) {
                    float2 u = *(const float2*)(orow + c);
                    float2 o = {silu(v0) * u.x, silu(v1) * u.y};
                    *(float2*)(orow + c) = o;
                } else {  // EPI_ATOMIC
                    atomicAdd(orow + c,     w * v0);
                    atomicAdd(orow + c + 1, w * v1);
                }
            }
        }
    }
}

// ---------------- prep / router ------------------------------------------------
__global__ void zero_cnt_kernel() {
    if (threadIdx.x < E) g_cnt[threadIdx.x] = 0;
}

__global__ void router_kernel(const float* __restrict__ x,
                              const float* __restrict__ rw,
                              const float* __restrict__ bias) {
    int t    = blockIdx.x * (blockDim.x >> 5) + (threadIdx.x >> 5);
    int lane = threadIdx.x & 31;
    if (t >= T) return;
    const float4* xr = (const float4*)(x + (size_t)t * D);

    float logit[E];
#pragma unroll
    for (int e = 0; e < E; e++) {
        const float4* w = (const float4*)(rw + (size_t)e * D);
        float p = 0.f;
        for (int k = lane; k < D / 4; k += 32) {
            float4 a = xr[k], b = w[k];
            p += a.x * b.x + a.y * b.y + a.z * b.z + a.w * b.w;
        }
#pragma unroll
        for (int o = 16; o > 0; o >>= 1) p += __shfl_xor_sync(0xffffffffu, p, o);
        logit[e] = p;
    }

    if (lane == 0) {
        float scores[E], s[E];
#pragma unroll
        for (int e = 0; e < E; e++) {
            scores[e] = 1.f / (1.f + expf(-logit[e]));
            s[e]      = scores[e] + bias[e];
        }
        float gs[NG];
#pragma unroll
        for (int g = 0; g < NG; g++) {
            float m1 = -1e30f, m2 = -1e30f;
#pragma unroll
            for (int j = 0; j < EPG; j++) {
                float v = s[g * EPG + j];
                if (v > m1) { m2 = m1; m1 = v; }
                else if (v > m2) { m2 = v; }
            }
            gs[g] = m1 + m2;
        }
        int g1 = 0; float b1 = -1e30f;
#pragma unroll
        for (int g = 0; g < NG; g++) if (gs[g] > b1) { b1 = gs[g]; g1 = g; }
        int g2 = -1; float b2 = -1e30f;
#pragma unroll
        for (int g = 0; g < NG; g++) if (g != g1 && gs[g] > b2) { b2 = gs[g]; g2 = g; }

        float masked[E];
#pragma unroll
        for (int e = 0; e < E; e++) {
            int g = e / EPG;
            masked[e] = (g == g1 || g == g2) ? s[e] : -1.0f;
        }
        int idx[KSEL]; bool taken[E];
#pragma unroll
        for (int e = 0; e < E; e++) taken[e] = false;
#pragma unroll
        for (int k = 0; k < KSEL; k++) {
            float best = -1e30f; int bi = 0;
#pragma unroll
            for (int e = 0; e < E; e++)
                if (!taken[e] && masked[e] > best) { best = masked[e]; bi = e; }
            taken[bi] = true;
            idx[k] = bi;
        }
        float tw[KSEL], sum = 0.f;
#pragma unroll
        for (int k = 0; k < KSEL; k++) { tw[k] = scores[idx[k]]; sum += tw[k]; }
        float inv = SCALEF / (sum + 1e-20f);
#pragma unroll
        for (int k = 0; k < KSEL; k++) {
            int e = idx[k];
            int pos = atomicAdd(&g_cnt[e], 1);
            g_tok[e * T + pos] = t;
            g_wt [e * T + pos] = tw[k] * inv;
        }
    }
}

// ---------------- launch -------------------------------------------------------
extern "C" void kernel_launch(void* const* d_in, const int* in_sizes, int n_in,
                              void* d_out, int out_size) {
    const float* x      = (const float*)d_in[0];
    const float* rw     = (const float*)d_in[1];
    const float* bias   = (const float*)d_in[2];
    const float* gate_w = (const float*)d_in[3];   // [E][D][F] k-major
    const float* up_w   = (const float*)d_in[4];   // [E][D][F]
    const float* down_w = (const float*)d_in[5];   // [E][F][D]
    const float* shg    = (const float*)d_in[6];   // [D][SHF]
    const float* shu    = (const float*)d_in[7];   // [D][SHF]
    const float* shd    = (const float*)d_in[8];   // [SHF][D]
    float* out = (float*)d_out;

    float *p_act, *p_shact;
    cudaGetSymbolAddress((void**)&p_act,   g_act);
    cudaGetSymbolAddress((void**)&p_shact, g_shact);

    zero_cnt_kernel<<<1, 32>>>();
    router_kernel<<<T / 8, 256>>>(x, rw, bias);

    // routed up: out = x(gather) @ up_w[e]  -> g_act raw
    gemm_mma<EPI_RAW, true><<<dim3(F / 128, T / 128, E), 256>>>(
        x, up_w, p_act, D, (size_t)D * F, F, F, 1);
    // routed gate: g_act = silu(x @ gate_w[e]) * g_act
    gemm_mma<EPI_SILU_MUL, true><<<dim3(F / 128, T / 128, E), 256>>>(
        x, gate_w, p_act, D, (size_t)D * F, F, F, 1);
    // shared up: g_shact = x @ sh_up (raw)
    gemm_mma<EPI_RAW, false><<<dim3(SHF / 128, T / 128, 1), 256>>>(
        x, shu, p_shact, D, 0, SHF, SHF, 0);
    // shared gate: g_shact = silu(x @ sh_gate) * g_shact
    gemm_mma<EPI_SILU_MUL, false><<<dim3(SHF / 128, T / 128, 1), 256>>>(
        x, shg, p_shact, D, 0, SHF, SHF, 0);
    // shared down: out = g_shact @ sh_down (plain store initializes out)
    gemm_mma<EPI_STORE, false><<<dim3(D / 128, T / 128, 1), 256>>>(
        p_shact, shd, out, SHF, 0, D, D, 0);
    // routed down: out += w * (g_act @ down_w[e])  (atomic combine)
    gemm_mma<EPI_ATOMIC, false><<<dim3(D / 128, T / 128, E), 256>>>(
        p_act, down_w, out, F, (size_t)F * D, D, D, 1);
}

// round 6
// speedup vs baseline: 2.5839x; 1.5967x over previous
#include <cuda_runtime.h>
#include <math.h>
#include <stdint.h>

#define T    2048
#define D    1024
#define E    16
#define KSEL 4
#define NG   4
#define EPG  4
#define F    1024
#define SHF  2048
#define SCALEF 2.5f

// ---------------- scratch ------------------------------------------------------
__device__ int   g_cnt[E];
__device__ int   g_tok[E * T];
__device__ float g_wt [E * T];
__device__ float g_xa [(size_t)T * D];        // x, tf32-rounded
__device__ float g_act [(size_t)E * T * F];   // routed silu(g)*u (tf32-rounded)
__device__ float g_shact[(size_t)T * SHF];    // shared silu(g)*u (tf32-rounded)

// ---------------- helpers ------------------------------------------------------
__device__ __forceinline__ uint32_t su32(const void* p) {
    uint32_t a;
    asm("{ .reg .u64 t; cvta.to.shared.u64 t, %1; cvt.u32.u64 %0, t; }"
        : "=r"(a) : "l"(p));
    return a;
}
__device__ __forceinline__ uint32_t f2tf32(float x) {
    uint32_t o;
    asm("cvt.rna.tf32.f32 %0, %1;" : "=r"(o) : "f"(x));
    return o;
}
__device__ __forceinline__ float silu(float g) { return g / (1.f + expf(-g)); }

__device__ __forceinline__ void cp16(float* smem_dst, const float* gsrc) {
    asm volatile("cp.async.cg.shared.global [%0], [%1], 16;"
                 :: "r"(su32(smem_dst)), "l"(gsrc));
}
#define CP_COMMIT() asm volatile("cp.async.commit_group;" ::: "memory")
#define CP_WAIT1()  asm volatile("cp.async.wait_group 1;" ::: "memory")

__device__ __forceinline__ void mma_tf32(float c[4], const uint32_t a[4],
                                         const uint32_t b[2]) {
    asm volatile(
        "mma.sync.aligned.m16n8k8.row.col.f32.tf32.tf32.f32 "
        "{%0,%1,%2,%3}, {%4,%5,%6,%7}, {%8,%9}, {%0,%1,%2,%3};"
        : "+f"(c[0]), "+f"(c[1]), "+f"(c[2]), "+f"(c[3])
        : "r"(a[0]), "r"(a[1]), "r"(a[2]), "r"(a[3]), "r"(b[0]), "r"(b[1]));
}

#define ALD 36    // As stride: (4r+c)%32 conflict-free; 144B % 16 == 0
#define BLD 136   // Bs stride (down): (8r+c)%32 conflict-free; 544B % 16 == 0
#define GLD 72    // Bs stride (gateup, 64 cols): (8r+c)%32 conflict-free; 288B ok

// ================= fused gate+up GEMM (tile 128x64, K=D) ======================
// g = A@Bg, u = A@Bu; writes tf32(silu(g)*u) into Oact.
template <bool GATHER>
__global__ void __launch_bounds__(256, 2)
gateup_mma(const float* __restrict__ A, const float* __restrict__ Bg,
           const float* __restrict__ Bu, float* __restrict__ Oact,
           int BN, size_t b_exp_stride, int use_expert) {
    const int e   = use_expert ? blockIdx.z : 0;
    const int cnt = use_expert ? g_cnt[e] : T;
    const int m0  = blockIdx.y * 128;
    if (m0 >= cnt) return;
    const int n0  = blockIdx.x * 64;

    extern __shared__ float sm[];
    float* AS  = sm;                       // [2][128][ALD]
    float* BGS = sm + 2 * 128 * ALD;       // [2][32][GLD]
    float* BUS = BGS + 2 * 32 * GLD;       // [2][32][GLD]
    int*   rows = (int*)(BUS + 2 * 32 * GLD);

    const int tid  = threadIdx.x;
    const int lane = tid & 31;
    const int wid  = tid >> 5;
    const int warp_m = wid & 3;            // 4 warps x 32 rows
    const int warp_n = wid >> 2;           // 2 warps x 32 cols

    if (tid < 128) {
        if (GATHER) {
            int i = m0 + tid;
            rows[tid] = g_tok[e * T + (i < cnt ? i : cnt - 1)];
        } else {
            rows[tid] = m0 + tid;
        }
    }
    __syncthreads();

    const int aRow = tid >> 1, aCol = (tid & 1) * 16;
    const int bRow = tid >> 3, bCol = (tid & 7) * 8;

    const float* aG  = A + (size_t)rows[aRow] * D + aCol;
    const float* bgG = Bg + (use_expert ? (size_t)e * b_exp_stride : 0) +
                       (size_t)bRow * BN + n0 + bCol;
    const float* buG = Bu + (use_expert ? (size_t)e * b_exp_stride : 0) +
                       (size_t)bRow * BN + n0 + bCol;

    float ag[2][4][4], au[2][4][4];
#pragma unroll
    for (int mt = 0; mt < 2; mt++)
#pragma unroll
        for (int nt = 0; nt < 4; nt++)
#pragma unroll
            for (int j = 0; j < 4; j++) { ag[mt][nt][j] = 0.f; au[mt][nt][j] = 0.f; }

    // prologue: stage 0
    {
        float* ad = AS + aRow * ALD + aCol;
        cp16(ad, aG); cp16(ad + 4, aG + 4); cp16(ad + 8, aG + 8); cp16(ad + 12, aG + 12);
        float* gd = BGS + bRow * GLD + bCol;
        cp16(gd, bgG); cp16(gd + 4, bgG + 4);
        float* ud = BUS + bRow * GLD + bCol;
        cp16(ud, buG); cp16(ud + 4, buG + 4);
    }
    CP_COMMIT();

    int buf = 0;
    for (int k0 = 0; k0 < D; k0 += 32) {
        if (k0 + 32 < D) {
            int s = buf ^ 1;
            const float* ap = aG + k0 + 32;
            float* ad = AS + s * 128 * ALD + aRow * ALD + aCol;
            cp16(ad, ap); cp16(ad + 4, ap + 4); cp16(ad + 8, ap + 8); cp16(ad + 12, ap + 12);
            const float* gp = bgG + (size_t)(k0 + 32) * BN;
            float* gd = BGS + s * 32 * GLD + bRow * GLD + bCol;
            cp16(gd, gp); cp16(gd + 4, gp + 4);
            const float* up = buG + (size_t)(k0 + 32) * BN;
            float* ud = BUS + s * 32 * GLD + bRow * GLD + bCol;
            cp16(ud, up); cp16(ud + 4, up + 4);
        }
        CP_COMMIT();
        CP_WAIT1();
        __syncthreads();

        const float* as = AS + buf * 128 * ALD;
        const float* bg = BGS + buf * 32 * GLD;
        const float* bu = BUS + buf * 32 * GLD;
#pragma unroll
        for (int ks = 0; ks < 4; ks++) {
            const int kb = ks * 8;
            uint32_t af[2][4];
#pragma unroll
            for (int mt = 0; mt < 2; mt++) {
                int r = warp_m * 32 + mt * 16 + (lane >> 2);
                int c = kb + (lane & 3);
                af[mt][0] = __float_as_uint(as[r * ALD + c]);
                af[mt][1] = __float_as_uint(as[(r + 8) * ALD + c]);
                af[mt][2] = __float_as_uint(as[r * ALD + c + 4]);
                af[mt][3] = __float_as_uint(as[(r + 8) * ALD + c + 4]);
            }
            uint32_t bfg[4][2], bfu[4][2];
#pragma unroll
            for (int nt = 0; nt < 4; nt++) {
                int cc = warp_n * 32 + nt * 8 + (lane >> 2);
                int rr = kb + (lane & 3);
                bfg[nt][0] = f2tf32(bg[rr * GLD + cc]);
                bfg[nt][1] = f2tf32(bg[(rr + 4) * GLD + cc]);
                bfu[nt][0] = f2tf32(bu[rr * GLD + cc]);
                bfu[nt][1] = f2tf32(bu[(rr + 4) * GLD + cc]);
            }
#pragma unroll
            for (int mt = 0; mt < 2; mt++)
#pragma unroll
                for (int nt = 0; nt < 4; nt++) {
                    mma_tf32(ag[mt][nt], af[mt], bfg[nt]);
                    mma_tf32(au[mt][nt], af[mt], bfu[nt]);
                }
        }
        __syncthreads();
        buf ^= 1;
    }

    // epilogue: write tf32(silu(g)*u)
#pragma unroll
    for (int mt = 0; mt < 2; mt++) {
#pragma unroll
        for (int half = 0; half < 2; half++) {
            const int m = m0 + warp_m * 32 + mt * 16 + (lane >> 2) + half * 8;
            if (m >= cnt) continue;
            float* orow = use_expert
                ? Oact + ((size_t)e * T + m) * F + n0
                : Oact + (size_t)m * SHF + n0;
#pragma unroll
            for (int nt = 0; nt < 4; nt++) {
                const int c = warp_n * 32 + nt * 8 + 2 * (lane & 3);
                float g0 = ag[mt][nt][half * 2 + 0], u0 = au[mt][nt][half * 2 + 0];
                float g1 = ag[mt][nt][half * 2 + 1], u1 = au[mt][nt][half * 2 + 1];
                float2 o;
                o.x = __uint_as_float(f2tf32(silu(g0) * u0));
                o.y = __uint_as_float(f2tf32(silu(g1) * u1));
                *(float2*)(orow + c) = o;
            }
        }
    }
}

// ================= down GEMM (tile 128x128) ===================================
#define EPI_STORE  2
#define EPI_ATOMIC 3

template <int MODE>
__global__ void __launch_bounds__(256, 2)
down_mma(const float* __restrict__ A, const float* __restrict__ B,
         float* __restrict__ O, int K, size_t b_exp_stride, int use_expert) {
    const int e   = use_expert ? blockIdx.z : 0;
    const int cnt = use_expert ? g_cnt[e] : T;
    const int m0  = blockIdx.y * 128;
    if (m0 >= cnt) return;
    const int n0  = blockIdx.x * 128;

    extern __shared__ float sm[];
    float* AS = sm;                    // [2][128][ALD]
    float* BS = sm + 2 * 128 * ALD;    // [2][32][BLD]

    const int tid  = threadIdx.x;
    const int lane = tid & 31;
    const int wid  = tid >> 5;
    const int warp_m = wid & 3;
    const int warp_n = wid >> 2;       // 2 warps x 64 cols

    const int aRow = tid >> 1, aCol = (tid & 1) * 16;
    const int bRow = tid >> 3, bCol = (tid & 7) * 16;

    const float* aG = A + (use_expert ? (size_t)e * T * K : 0) +
                      (size_t)(m0 + aRow) * K + aCol;
    const float* bG = B + (use_expert ? (size_t)e * b_exp_stride : 0) +
                      (size_t)bRow * D + n0 + bCol;

    float acc[2][8][4];
#pragma unroll
    for (int mt = 0; mt < 2; mt++)
#pragma unroll
        for (int nt = 0; nt < 8; nt++)
#pragma unroll
            for (int j = 0; j < 4; j++) acc[mt][nt][j] = 0.f;

    {
        float* ad = AS + aRow * ALD + aCol;
        cp16(ad, aG); cp16(ad + 4, aG + 4); cp16(ad + 8, aG + 8); cp16(ad + 12, aG + 12);
        float* bd = BS + bRow * BLD + bCol;
        cp16(bd, bG); cp16(bd + 4, bG + 4); cp16(bd + 8, bG + 8); cp16(bd + 12, bG + 12);
    }
    CP_COMMIT();

    int buf = 0;
    for (int k0 = 0; k0 < K; k0 += 32) {
        if (k0 + 32 < K) {
            int s = buf ^ 1;
            const float* ap = aG + k0 + 32;
            float* ad = AS + s * 128 * ALD + aRow * ALD + aCol;
            cp16(ad, ap); cp16(ad + 4, ap + 4); cp16(ad + 8, ap + 8); cp16(ad + 12, ap + 12);
            const float* bp = bG + (size_t)(k0 + 32) * D;
            float* bd = BS + s * 32 * BLD + bRow * BLD + bCol;
            cp16(bd, bp); cp16(bd + 4, bp + 4); cp16(bd + 8, bp + 8); cp16(bd + 12, bp + 12);
        }
        CP_COMMIT();
        CP_WAIT1();
        __syncthreads();

        const float* as = AS + buf * 128 * ALD;
        const float* bs = BS + buf * 32 * BLD;
#pragma unroll
        for (int ks = 0; ks < 4; ks++) {
            const int kb = ks * 8;
            uint32_t af[2][4];
#pragma unroll
            for (int mt = 0; mt < 2; mt++) {
                int r = warp_m * 32 + mt * 16 + (lane >> 2);
                int c = kb + (lane & 3);
                af[mt][0] = __float_as_uint(as[r * ALD + c]);       // A pre-rounded
                af[mt][1] = __float_as_uint(as[(r + 8) * ALD + c]);
                af[mt][2] = __float_as_uint(as[r * ALD + c + 4]);
                af[mt][3] = __float_as_uint(as[(r + 8) * ALD + c + 4]);
            }
            uint32_t bf[8][2];
#pragma unroll
            for (int nt = 0; nt < 8; nt++) {
                int cc = warp_n * 64 + nt * 8 + (lane >> 2);
                int rr = kb + (lane & 3);
                bf[nt][0] = f2tf32(bs[rr * BLD + cc]);
                bf[nt][1] = f2tf32(bs[(rr + 4) * BLD + cc]);
            }
#pragma unroll
            for (int mt = 0; mt < 2; mt++)
#pragma unroll
                for (int nt = 0; nt < 8; nt++)
                    mma_tf32(acc[mt][nt], af[mt], bf[nt]);
        }
        __syncthreads();
        buf ^= 1;
    }

#pragma unroll
    for (int mt = 0; mt < 2; mt++) {
#pragma unroll
        for (int half = 0; half < 2; half++) {
            const int m = m0 + warp_m * 32 + mt * 16 + (lane >> 2) + half * 8;
            if (m >= cnt) continue;
            int   tok = m;
            float w   = 1.f;
            if (MODE == EPI_ATOMIC) { tok = g_tok[e * T + m]; w = g_wt[e * T + m]; }
            float* orow = O + (size_t)tok * D + n0;
#pragma unroll
            for (int nt = 0; nt < 8; nt++) {
                const int c = warp_n * 64 + nt * 8 + 2 * (lane & 3);
                float v0 = acc[mt][nt][half * 2 + 0];
                float v1 = acc[mt][nt][half * 2 + 1];
                if (MODE == EPI_STORE) {
                    float2 o = {v0, v1};
                    *(float2*)(orow + c) = o;
                } else {
                    atomicAdd(orow + c,     w * v0);
                    atomicAdd(orow + c + 1, w * v1);
                }
            }
        }
    }
}

// ---------------- prep / router ------------------------------------------------
__global__ void zero_cnt_kernel() {
    if (threadIdx.x < E) g_cnt[threadIdx.x] = 0;
}

__global__ void cvtx_kernel(const float* __restrict__ x) {
    size_t i = ((size_t)blockIdx.x * 256 + threadIdx.x) * 4;
    float4 v = *(const float4*)(x + i);
    v.x = __uint_as_float(f2tf32(v.x)); v.y = __uint_as_float(f2tf32(v.y));
    v.z = __uint_as_float(f2tf32(v.z)); v.w = __uint_as_float(f2tf32(v.w));
    *(float4*)(g_xa + i) = v;
}

__global__ void router_kernel(const float* __restrict__ x,
                              const float* __restrict__ rw,
                              const float* __restrict__ bias) {
    int t    = blockIdx.x * (blockDim.x >> 5) + (threadIdx.x >> 5);
    int lane = threadIdx.x & 31;
    if (t >= T) return;
    const float4* xr = (const float4*)(x + (size_t)t * D);

    float logit[E];
#pragma unroll
    for (int e = 0; e < E; e++) {
        const float4* w = (const float4*)(rw + (size_t)e * D);
        float p = 0.f;
        for (int k = lane; k < D / 4; k += 32) {
            float4 a = xr[k], b = w[k];
            p += a.x * b.x + a.y * b.y + a.z * b.z + a.w * b.w;
        }
#pragma unroll
        for (int o = 16; o > 0; o >>= 1) p += __shfl_xor_sync(0xffffffffu, p, o);
        logit[e] = p;
    }

    if (lane == 0) {
        float scores[E], s[E];
#pragma unroll
        for (int e = 0; e < E; e++) {
            scores[e] = 1.f / (1.f + expf(-logit[e]));
            s[e]      = scores[e] + bias[e];
        }
        float gs[NG];
#pragma unroll
        for (int g = 0; g < NG; g++) {
            float m1 = -1e30f, m2 = -1e30f;
#pragma unroll
            for (int j = 0; j < EPG; j++) {
                float v = s[g * EPG + j];
                if (v > m1) { m2 = m1; m1 = v; }
                else if (v > m2) { m2 = v; }
            }
            gs[g] = m1 + m2;
        }
        int g1 = 0; float b1 = -1e30f;
#pragma unroll
        for (int g = 0; g < NG; g++) if (gs[g] > b1) { b1 = gs[g]; g1 = g; }
        int g2 = -1; float b2 = -1e30f;
#pragma unroll
        for (int g = 0; g < NG; g++) if (g != g1 && gs[g] > b2) { b2 = gs[g]; g2 = g; }

        float masked[E];
#pragma unroll
        for (int e = 0; e < E; e++) {
            int g = e / EPG;
            masked[e] = (g == g1 || g == g2) ? s[e] : -1.0f;
        }
        int idx[KSEL]; bool taken[E];
#pragma unroll
        for (int e = 0; e < E; e++) taken[e] = false;
#pragma unroll
        for (int k = 0; k < KSEL; k++) {
            float best = -1e30f; int bi = 0;
#pragma unroll
            for (int e = 0; e < E; e++)
                if (!taken[e] && masked[e] > best) { best = masked[e]; bi = e; }
            taken[bi] = true;
            idx[k] = bi;
        }
        float tw[KSEL], sum = 0.f;
#pragma unroll
        for (int k = 0; k < KSEL; k++) { tw[k] = scores[idx[k]]; sum += tw[k]; }
        float inv = SCALEF / (sum + 1e-20f);
#pragma unroll
        for (int k = 0; k < KSEL; k++) {
            int e = idx[k];
            int pos = atomicAdd(&g_cnt[e], 1);
            g_tok[e * T + pos] = t;
            g_wt [e * T + pos] = tw[k] * inv;
        }
    }
}

// ---------------- launch -------------------------------------------------------
#define GU_SMEM (2 * 128 * ALD * 4 + 2 * 2 * 32 * GLD * 4 + 128 * 4)
#define DN_SMEM (2 * 128 * ALD * 4 + 2 * 32 * BLD * 4)

extern "C" void kernel_launch(void* const* d_in, const int* in_sizes, int n_in,
                              void* d_out, int out_size) {
    const float* x      = (const float*)d_in[0];
    const float* rw     = (const float*)d_in[1];
    const float* bias   = (const float*)d_in[2];
    const float* gate_w = (const float*)d_in[3];   // [E][D][F]
    const float* up_w   = (const float*)d_in[4];   // [E][D][F]
    const float* down_w = (const float*)d_in[5];   // [E][F][D]
    const float* shg    = (const float*)d_in[6];   // [D][SHF]
    const float* shu    = (const float*)d_in[7];   // [D][SHF]
    const float* shd    = (const float*)d_in[8];   // [SHF][D]
    float* out = (float*)d_out;

    float *p_xa, *p_act, *p_shact;
    cudaGetSymbolAddress((void**)&p_xa,    g_xa);
    cudaGetSymbolAddress((void**)&p_act,   g_act);
    cudaGetSymbolAddress((void**)&p_shact, g_shact);

    static int attr_done = 0;
    if (!attr_done) {
        cudaFuncSetAttribute(gateup_mma<true>,
                             cudaFuncAttributeMaxDynamicSharedMemorySize, GU_SMEM);
        cudaFuncSetAttribute(gateup_mma<false>,
                             cudaFuncAttributeMaxDynamicSharedMemorySize, GU_SMEM);
        cudaFuncSetAttribute(down_mma<EPI_STORE>,
                             cudaFuncAttributeMaxDynamicSharedMemorySize, DN_SMEM);
        cudaFuncSetAttribute(down_mma<EPI_ATOMIC>,
                             cudaFuncAttributeMaxDynamicSharedMemorySize, DN_SMEM);
        attr_done = 1;
    }

    zero_cnt_kernel<<<1, 32>>>();
    router_kernel<<<T / 8, 256>>>(x, rw, bias);
    cvtx_kernel<<<(T * D) / 1024, 256>>>(x);

    // routed gate+up fused: g_act = tf32(silu(x@gate)*(x@up))
    gateup_mma<true><<<dim3(F / 64, T / 128, E), 256, GU_SMEM>>>(
        p_xa, gate_w, up_w, p_act, F, (size_t)D * F, 1);
    // shared gate+up fused
    gateup_mma<false><<<dim3(SHF / 64, T / 128, 1), 256, GU_SMEM>>>(
        p_xa, shg, shu, p_shact, SHF, 0, 0);
    // shared down: plain store initializes out
    down_mma<EPI_STORE><<<dim3(D / 128, T / 128, 1), 256, DN_SMEM>>>(
        p_shact, shd, out, SHF, 0, 0);
    // routed down: weighted atomic combine
    down_mma<EPI_ATOMIC><<<dim3(D / 128, T / 128, E), 256, DN_SMEM>>>(
        p_act, down_w, out, F, (size_t)F * D, 1);
}